// round 3
// baseline (speedup 1.0000x reference)
#include <cuda_runtime.h>

// ---------------------------------------------------------------------------
// SE3 loss:
//   rot_loss = mean( (polar_norm(pred_R)^T @ polar_norm(quat_to_R(gt_q)) - I)^2 )
//   t_loss   = mean( (pred_t - gt_t)^2 )
// where polar_norm(R) = sign(det R) * (orthogonal polar factor of R),
// matching the reference's SVD-based normalize exactly (up to fp32 rounding).
// Polar factor via scaled Newton iteration X <- 0.5*(mu*X + (1/mu)*X^{-T}).
// ---------------------------------------------------------------------------

__device__ double g_accum;

__global__ void k_zero() { g_accum = 0.0; }

__global__ void k_final(float* out, int B) {
    *out = (float)(g_accum / (double)B);
}

// fast approx transcendentals (explicit PTX; don't rely on --use_fast_math)
__device__ __forceinline__ float frcp(float x)  { float r; asm("rcp.approx.f32 %0, %1;"   : "=f"(r) : "f"(x)); return r; }
__device__ __forceinline__ float frsq(float x)  { float r; asm("rsqrt.approx.f32 %0, %1;" : "=f"(r) : "f"(x)); return r; }
__device__ __forceinline__ float fsqr(float x)  { float r; asm("sqrt.approx.f32 %0, %1;"  : "=f"(r) : "f"(x)); return r; }

// In-place polar factor of row-major 3x3 X (X[3*i+j]).
// Returns sign(det) of the ORIGINAL matrix.
// Scaled Newton: X <- 0.5*(mu*X + (1/mu)*X^{-T}),  mu = (|X^{-1}|_F^2/|X|_F^2)^{1/4}.
// X^{-T} = cofactor(X)/det, cofactor matrix has the SAME row-major indexing.
__device__ __forceinline__ float polar3x3(float X[9]) {
    float sgn = 1.0f;
    #pragma unroll
    for (int it = 0; it < 6; ++it) {
        // cofactor matrix C(i,j), row-major c[3i+j]
        float c0 = fmaf(X[4], X[8], -X[5]*X[7]);
        float c1 = fmaf(X[5], X[6], -X[3]*X[8]);
        float c2 = fmaf(X[3], X[7], -X[4]*X[6]);
        float c3 = fmaf(X[2], X[7], -X[1]*X[8]);
        float c4 = fmaf(X[0], X[8], -X[2]*X[6]);
        float c5 = fmaf(X[1], X[6], -X[0]*X[7]);
        float c6 = fmaf(X[1], X[5], -X[2]*X[4]);
        float c7 = fmaf(X[2], X[3], -X[0]*X[5]);
        float c8 = fmaf(X[0], X[4], -X[1]*X[3]);
        float det = fmaf(X[0], c0, fmaf(X[1], c1, X[2]*c2));
        if (it == 0 && det < 0.0f) sgn = -1.0f;
        float rdet = frcp(det);

        float nx = X[0]*X[0];
        #pragma unroll
        for (int i = 1; i < 9; ++i) nx = fmaf(X[i], X[i], nx);
        float nc = c0*c0;
        nc = fmaf(c1,c1,nc); nc = fmaf(c2,c2,nc); nc = fmaf(c3,c3,nc);
        nc = fmaf(c4,c4,nc); nc = fmaf(c5,c5,nc); nc = fmaf(c6,c6,nc);
        nc = fmaf(c7,c7,nc); nc = fmaf(c8,c8,nc);

        // r = |X^{-1}|^2/|X|^2 = nc*rdet^2/nx ;  mu = r^{1/4}
        float r   = nc * rdet * rdet * frcp(nx);
        float mu2 = fsqr(r);              // sqrt(r) = mu^2
        float a   = 0.5f * fsqr(mu2);     // 0.5*mu
        float b   = 0.5f * rdet * frsq(mu2); // 0.5*(1/mu)*rdet

        X[0] = fmaf(a, X[0], b*c0);
        X[1] = fmaf(a, X[1], b*c1);
        X[2] = fmaf(a, X[2], b*c2);
        X[3] = fmaf(a, X[3], b*c3);
        X[4] = fmaf(a, X[4], b*c4);
        X[5] = fmaf(a, X[5], b*c5);
        X[6] = fmaf(a, X[6], b*c6);
        X[7] = fmaf(a, X[7], b*c7);
        X[8] = fmaf(a, X[8], b*c8);
    }
    return sgn;
}

__global__ void se3_loss_kernel(const float* __restrict__ pred_R,
                                const float* __restrict__ pred_t,
                                const float* __restrict__ gt,
                                int B) {
    int idx = blockIdx.x * blockDim.x + threadIdx.x;
    float v = 0.0f;

    if (idx < B) {
        // ---- pred rotation: polar-normalize ----
        float P[9];
        const float* rp = pred_R + (size_t)idx * 9;
        #pragma unroll
        for (int i = 0; i < 9; ++i) P[i] = rp[i];
        float sp = polar3x3(P);

        // ---- gt: quat (unnormalized) -> matrix -> polar-normalize ----
        const float* g = gt + (size_t)idx * 7;
        float qw = g[0], qx = g[1], qy = g[2], qz = g[3];
        float G[9];
        G[0] = 1.0f - 2.0f*(qy*qy + qz*qz);
        G[1] = 2.0f*(qx*qy - qw*qz);
        G[2] = 2.0f*(qx*qz + qw*qy);
        G[3] = 2.0f*(qx*qy + qw*qz);
        G[4] = 1.0f - 2.0f*(qx*qx + qz*qz);
        G[5] = 2.0f*(qy*qz - qw*qx);
        G[6] = 2.0f*(qx*qz - qw*qy);
        G[7] = 2.0f*(qy*qz + qw*qx);
        G[8] = 1.0f - 2.0f*(qx*qx + qy*qy);
        float sg = polar3x3(G);

        float sig = sp * sg;

        // ---- M = P^T @ G ; rot contribution ----
        float rot = 0.0f;
        #pragma unroll
        for (int i = 0; i < 3; ++i) {
            #pragma unroll
            for (int k = 0; k < 3; ++k) {
                float m = fmaf(P[i], G[k], fmaf(P[3+i], G[3+k], P[6+i]*G[6+k]));
                m = sig * m - ((i == k) ? 1.0f : 0.0f);
                rot = fmaf(m, m, rot);
            }
        }

        // ---- translation ----
        const float* tp = pred_t + (size_t)idx * 3;
        float t0 = tp[0] - g[4];
        float t1 = tp[1] - g[5];
        float t2 = tp[2] - g[6];
        float tl = fmaf(t0, t0, fmaf(t1, t1, t2*t2));

        v = rot * (1.0f/9.0f) + tl * (1.0f/3.0f);
    }

    // ---- block reduction ----
    #pragma unroll
    for (int o = 16; o > 0; o >>= 1) v += __shfl_xor_sync(0xFFFFFFFFu, v, o);

    __shared__ float sh[32];
    int lane = threadIdx.x & 31;
    int warp = threadIdx.x >> 5;
    if (lane == 0) sh[warp] = v;
    __syncthreads();
    if (warp == 0) {
        int nw = (blockDim.x + 31) >> 5;
        v = (lane < nw) ? sh[lane] : 0.0f;
        #pragma unroll
        for (int o = 16; o > 0; o >>= 1) v += __shfl_xor_sync(0xFFFFFFFFu, v, o);
        if (lane == 0) atomicAdd(&g_accum, (double)v);
    }
}

extern "C" void kernel_launch(void* const* d_in, const int* in_sizes, int n_in,
                              void* d_out, int out_size) {
    (void)n_in; (void)out_size;
    const float* pred_R = (const float*)d_in[0];
    const float* pred_t = (const float*)d_in[1];
    const float* gt     = (const float*)d_in[2];
    int B = in_sizes[0] / 9;

    k_zero<<<1, 1>>>();
    const int threads = 256;
    int blocks = (B + threads - 1) / threads;
    se3_loss_kernel<<<blocks, threads>>>(pred_R, pred_t, gt, B);
    k_final<<<1, 1>>>((float*)d_out, B);
}

// round 4
// speedup vs baseline: 1.2959x; 1.2959x over previous
#include <cuda_runtime.h>

// ---------------------------------------------------------------------------
// SE3 loss, single fused kernel:
//   rot_loss = mean( (polar_norm(pred_R)^T @ polar_norm(quat_to_R(gt_q)) - I)^2 )
//   t_loss   = mean( (pred_t - gt_t)^2 )
// polar_norm(R) = sign(det R) * polar factor, via scaled Newton iteration.
// Grid-wide reduction with last-block-done finalize; the last block resets the
// device-global accumulator/counter so every graph replay is identical.
// ---------------------------------------------------------------------------

#define TPB 256

__device__ double g_accum = 0.0;          // zero at module load; reset each launch
__device__ unsigned int g_count = 0u;

__device__ __forceinline__ float frcp(float x)  { float r; asm("rcp.approx.f32 %0, %1;"   : "=f"(r) : "f"(x)); return r; }
__device__ __forceinline__ float frsq(float x)  { float r; asm("rsqrt.approx.f32 %0, %1;" : "=f"(r) : "f"(x)); return r; }
__device__ __forceinline__ float fsqr(float x)  { float r; asm("sqrt.approx.f32 %0, %1;"  : "=f"(r) : "f"(x)); return r; }

// In-place polar factor of row-major 3x3. Returns sign(det) of the original.
// Iters 0..2: Frobenius-scaled Newton  X <- 0.5*(mu*X + (1/mu)*X^{-T})
// Iters 3..4: plain Newton             X <- 0.5*(X + X^{-T})
__device__ __forceinline__ float polar3x3(float X[9]) {
    float sgn = 1.0f;
    #pragma unroll
    for (int it = 0; it < 5; ++it) {
        // cofactor matrix, row-major (so X^{-T} = C * (1/det))
        float c0 = fmaf(X[4], X[8], -X[5]*X[7]);
        float c1 = fmaf(X[5], X[6], -X[3]*X[8]);
        float c2 = fmaf(X[3], X[7], -X[4]*X[6]);
        float c3 = fmaf(X[2], X[7], -X[1]*X[8]);
        float c4 = fmaf(X[0], X[8], -X[2]*X[6]);
        float c5 = fmaf(X[1], X[6], -X[0]*X[7]);
        float c6 = fmaf(X[1], X[5], -X[2]*X[4]);
        float c7 = fmaf(X[2], X[3], -X[0]*X[5]);
        float c8 = fmaf(X[0], X[4], -X[1]*X[3]);
        float det = fmaf(X[0], c0, fmaf(X[1], c1, X[2]*c2));
        if (it == 0 && det < 0.0f) sgn = -1.0f;
        float rdet = frcp(det);

        float a, b;
        if (it < 3) {
            float nx = X[0]*X[0];
            #pragma unroll
            for (int i = 1; i < 9; ++i) nx = fmaf(X[i], X[i], nx);
            float nc = c0*c0;
            nc = fmaf(c1,c1,nc); nc = fmaf(c2,c2,nc); nc = fmaf(c3,c3,nc);
            nc = fmaf(c4,c4,nc); nc = fmaf(c5,c5,nc); nc = fmaf(c6,c6,nc);
            nc = fmaf(c7,c7,nc); nc = fmaf(c8,c8,nc);
            // r = |X^{-1}|^2/|X|^2 ; mu = r^{1/4}
            float r   = nc * rdet * rdet * frcp(nx);
            float mu2 = fsqr(r);                 // mu^2
            a = 0.5f * fsqr(mu2);                // 0.5*mu
            b = 0.5f * rdet * frsq(mu2);         // 0.5*(1/mu)/det
        } else {
            a = 0.5f;
            b = 0.5f * rdet;
        }

        X[0] = fmaf(a, X[0], b*c0);
        X[1] = fmaf(a, X[1], b*c1);
        X[2] = fmaf(a, X[2], b*c2);
        X[3] = fmaf(a, X[3], b*c3);
        X[4] = fmaf(a, X[4], b*c4);
        X[5] = fmaf(a, X[5], b*c5);
        X[6] = fmaf(a, X[6], b*c6);
        X[7] = fmaf(a, X[7], b*c7);
        X[8] = fmaf(a, X[8], b*c8);
    }
    return sgn;
}

__global__ void __launch_bounds__(TPB)
se3_loss_kernel(const float* __restrict__ pred_R,
                const float* __restrict__ pred_t,
                const float* __restrict__ gt,
                float* __restrict__ out,
                int B, int nblocks) {
    __shared__ float sR[TPB * 9];   // 9216 B
    __shared__ float sQ[TPB * 7];   // 7168 B
    __shared__ float sT[TPB * 3];   // 3072 B

    const int tid = threadIdx.x;
    const size_t base = (size_t)blockIdx.x * TPB;
    const bool full = (base + TPB <= (size_t)B);

    // ---- coalesced float4 staging into shared ----
    if (full) {
        const float4* r4 = (const float4*)(pred_R + base * 9);   // 576 float4
        float4* s4 = (float4*)sR;
        #pragma unroll
        for (int i = 0; i < 3; ++i) {
            int j = tid + i * TPB;
            if (j < (TPB*9)/4) s4[j] = r4[j];
        }
        const float4* q4 = (const float4*)(gt + base * 7);       // 448 float4
        float4* sq4 = (float4*)sQ;
        #pragma unroll
        for (int i = 0; i < 2; ++i) {
            int j = tid + i * TPB;
            if (j < (TPB*7)/4) sq4[j] = q4[j];
        }
        const float4* t4 = (const float4*)(pred_t + base * 3);   // 192 float4
        float4* st4 = (float4*)sT;
        if (tid < (TPB*3)/4) st4[tid] = t4[tid];
    } else {
        int n = (int)((size_t)B > base ? (size_t)B - base : 0);
        for (int j = tid; j < n * 9; j += TPB) sR[j] = pred_R[base * 9 + j];
        for (int j = tid; j < n * 7; j += TPB) sQ[j] = gt[base * 7 + j];
        for (int j = tid; j < n * 3; j += TPB) sT[j] = pred_t[base * 3 + j];
    }
    __syncthreads();

    float v = 0.0f;
    const int idx = (int)base + tid;
    if (idx < B) {
        // ---- pred rotation (stride 9 -> conflict-free LDS) ----
        float P[9];
        #pragma unroll
        for (int i = 0; i < 9; ++i) P[i] = sR[tid * 9 + i];
        float sp = polar3x3(P);

        // ---- gt quat -> matrix -> polar ----
        float qw = sQ[tid*7+0], qx = sQ[tid*7+1], qy = sQ[tid*7+2], qz = sQ[tid*7+3];
        float G[9];
        G[0] = 1.0f - 2.0f*(qy*qy + qz*qz);
        G[1] = 2.0f*(qx*qy - qw*qz);
        G[2] = 2.0f*(qx*qz + qw*qy);
        G[3] = 2.0f*(qx*qy + qw*qz);
        G[4] = 1.0f - 2.0f*(qx*qx + qz*qz);
        G[5] = 2.0f*(qy*qz - qw*qx);
        G[6] = 2.0f*(qx*qz - qw*qy);
        G[7] = 2.0f*(qy*qz + qw*qx);
        G[8] = 1.0f - 2.0f*(qx*qx + qy*qy);
        float sg = polar3x3(G);

        float sig = sp * sg;

        // ---- M = P^T @ G ; rot contribution ----
        float rot = 0.0f;
        #pragma unroll
        for (int i = 0; i < 3; ++i) {
            #pragma unroll
            for (int k = 0; k < 3; ++k) {
                float m = fmaf(P[i], G[k], fmaf(P[3+i], G[3+k], P[6+i]*G[6+k]));
                m = sig * m - ((i == k) ? 1.0f : 0.0f);
                rot = fmaf(m, m, rot);
            }
        }

        // ---- translation ----
        float t0 = sT[tid*3+0] - sQ[tid*7+4];
        float t1 = sT[tid*3+1] - sQ[tid*7+5];
        float t2 = sT[tid*3+2] - sQ[tid*7+6];
        float tl = fmaf(t0, t0, fmaf(t1, t1, t2*t2));

        v = rot * (1.0f/9.0f) + tl * (1.0f/3.0f);
    }

    // ---- block reduction ----
    #pragma unroll
    for (int o = 16; o > 0; o >>= 1) v += __shfl_xor_sync(0xFFFFFFFFu, v, o);

    __shared__ float sh[TPB / 32];
    int lane = tid & 31;
    int warp = tid >> 5;
    if (lane == 0) sh[warp] = v;
    __syncthreads();
    if (warp == 0) {
        v = (lane < TPB/32) ? sh[lane] : 0.0f;
        #pragma unroll
        for (int o = 16; o > 0; o >>= 1) v += __shfl_xor_sync(0xFFFFFFFFu, v, o);
        if (lane == 0) {
            atomicAdd(&g_accum, (double)v);
            __threadfence();
            unsigned int prev = atomicAdd(&g_count, 1u);
            if (prev == (unsigned int)(nblocks - 1)) {
                // last block: all other adds are visible (fence + atomic order)
                double total = atomicAdd(&g_accum, 0.0);   // atomic read at L2
                *out = (float)(total / (double)B);
                g_accum = 0.0;                              // reset for next replay
                g_count = 0u;
            }
        }
    }
}

extern "C" void kernel_launch(void* const* d_in, const int* in_sizes, int n_in,
                              void* d_out, int out_size) {
    (void)n_in; (void)out_size;
    const float* pred_R = (const float*)d_in[0];
    const float* pred_t = (const float*)d_in[1];
    const float* gt     = (const float*)d_in[2];
    int B = in_sizes[0] / 9;

    int blocks = (B + TPB - 1) / TPB;
    se3_loss_kernel<<<blocks, TPB>>>(pred_R, pred_t, gt, (float*)d_out, B, blocks);
}